// round 15
// baseline (speedup 1.0000x reference)
#include <cuda_runtime.h>

// Decoder_predict: batched greedy goals-NMS.  B=256, N=4096, T=30, K=6.
// scores = class * centerness, thr^2 = 4.0.
//
// V15: one kernel, two CTA roles.
//  Producers (blockIdx 0..1023; 4 per batch, 1024 cands, 256 thr): the
//    measured-good V13-A streaming shape (stream ONLY cls+cent via float4,
//    per-warp top-6, warp-0 rank-sort by count-of-greater). Warp 0 also
//    gathers the 6 winners' coords and writes complete float4 records
//    (x, y, score, idx) -> 24 records per batch; then release-fence +
//    per-batch atomic counter.
//  Finishers (blockIdx 1024..1279; one per batch): spin (volatile poll +
//    nanosleep) until the batch's 4 producers arrive, reset the counter
//    (graph-replay determinism), then: L2 record read -> rank + 24x24
//    conflict bitmask (one smem pass) -> single-thread exact greedy scan
//    (descending score, lowest-index ties, accept if no accepted point
//    within thr; fallback keeps sorted-first/goal-(0,0) semantics) ->
//    parallel traj gather (90 float4).
//  Dispatch order guarantees progress: all 1024 producers are scheduled
//  before any finisher; finishers never block producers.

#define NMS_B 256
#define NMS_N 4096
#define NMS_T 30
#define NMS_K 6
#define NMS_THR2 4.0f
#define THREADS 256
#define CTAS_PER_B 4
#define PROD_CTAS (NMS_B * CTAS_PER_B)   // 1024
#define CHUNK 1024
#define CTA_SURV 48                       // 8 warps * 6
#define B_SURV (CTAS_PER_B * NMS_K)       // 24 records per batch

__device__ float4       g_rec[NMS_B * B_SURV];   // x, y, score, idx(int bits)
__device__ unsigned int g_cnt[NMS_B];            // 0 -> 4 -> reset to 0

__global__ __launch_bounds__(THREADS)
void nms_persistent_kernel(const float* __restrict__ coord,  // [B,1,N,2]
                           const float* __restrict__ cls,    // [B,1,N]
                           const float* __restrict__ traj,   // [B,1,N,T,2]
                           const float* __restrict__ cent,   // [B,1,N]
                           float* __restrict__ out)
{
    const int blk  = blockIdx.x;
    const int tid  = threadIdx.x;
    const int wid  = tid >> 5;
    const int lane = tid & 31;

    if (blk < PROD_CTAS) {
        // ================= PRODUCER =================
        const int b = blk >> 2;
        const int q = blk & 3;

        __shared__ unsigned long long skey[CTA_SURV];

        {
            const float4* s4 = (const float4*)(cls  + (size_t)b * NMS_N + q * CHUNK);
            const float4* e4 = (const float4*)(cent + (size_t)b * NMS_N + q * CHUNK);
            const float4 sv = s4[tid];
            const float4 ev = e4[tid];

            unsigned sc[4];
            sc[0] = __float_as_uint(sv.x * ev.x);
            sc[1] = __float_as_uint(sv.y * ev.y);
            sc[2] = __float_as_uint(sv.z * ev.z);
            sc[3] = __float_as_uint(sv.w * ev.w);
            const unsigned i0 = (unsigned)(q * CHUNK + 4 * tid);

            unsigned tmax = max(max(sc[0], sc[1]), max(sc[2], sc[3]));

#pragma unroll
            for (int r = 0; r < NMS_K; r++) {
                unsigned m = tmax;
#pragma unroll
                for (int off = 16; off > 0; off >>= 1)
                    m = max(m, __shfl_xor_sync(0xFFFFFFFFu, m, off));

                if (m == 0u) {
                    // Degenerate (scores exhausted): unique tiny sentinel,
                    // sorts last, never collides with real keys.
                    if (lane == 0)
                        skey[wid * NMS_K + r] =
                            (unsigned long long)(wid * NMS_K + r + 1);
                } else {
                    const bool mine = (tmax == m);
                    const unsigned bal = __ballot_sync(0xFFFFFFFFu, mine);
                    const int wl = __ffs(bal) - 1;   // lowest lane = lowest idx
                    if (lane == wl) {
                        int jm = 3;
#pragma unroll
                        for (int j = 3; j >= 0; j--)
                            if (sc[j] == m) jm = j;  // lowest slot = lowest idx
                        skey[wid * NMS_K + r] =
                            ((unsigned long long)m << 32) | (unsigned)(~(i0 + jm));
#pragma unroll
                        for (int j = 0; j < 4; j++) if (j == jm) sc[j] = 0u;
                        tmax = max(max(sc[0], sc[1]), max(sc[2], sc[3]));
                    }
                }
            }
        }
        __syncthreads();

        // Warp 0: rank 48 survivors; winners gather coords, write records.
        if (wid == 0) {
            const unsigned long long k0 = skey[lane];
            const unsigned long long k1 = (lane < 16) ? skey[32 + lane] : 0ULL;
            int r0 = 0, r1 = 0;
#pragma unroll
            for (int j = 0; j < CTA_SURV; j++) {
                const unsigned long long kj = skey[j];
                r0 += (kj > k0);
                r1 += (kj > k1);
            }
            const float2* cptr = (const float2*)(coord + (size_t)b * NMS_N * 2);
            float4* dst = g_rec + (size_t)b * B_SURV + q * NMS_K;
            if (r0 < NMS_K) {
                const int idx = (int)(~(unsigned)k0) & (NMS_N - 1);
                const float2 c = cptr[idx];
                dst[r0] = make_float4(c.x, c.y,
                                      __uint_as_float((unsigned)(k0 >> 32)),
                                      __int_as_float(idx));
            }
            if (lane < 16 && r1 < NMS_K) {
                const int idx = (int)(~(unsigned)k1) & (NMS_N - 1);
                const float2 c = cptr[idx];
                dst[r1] = make_float4(c.x, c.y,
                                      __uint_as_float((unsigned)(k1 >> 32)),
                                      __int_as_float(idx));
            }
            __syncwarp();
            __threadfence();                       // release record writes
            if (lane == 0) atomicAdd(&g_cnt[b], 1u);
        }
        return;
    }

    // ================= FINISHER =================
    const int b = blk - PROD_CTAS;

    if (tid == 0) {
        volatile unsigned* p = &g_cnt[b];
        while (*p < (unsigned)CTAS_PER_B) __nanosleep(200);
        *p = 0u;                                   // reset for next replay
    }
    __syncthreads();
    __threadfence();                               // acquire side

    __shared__ float    sx[B_SURV], sy[B_SURV], ss[B_SURV];
    __shared__ int      si[B_SURV], ord[B_SURV];
    __shared__ unsigned long long fkey[B_SURV];
    __shared__ unsigned cm[B_SURV];
    __shared__ int      sel_pos[NMS_K];

    if (tid < B_SURV) {                            // one L2 trip
        const float4 v = __ldcg(&g_rec[(size_t)b * B_SURV + tid]);
        sx[tid] = v.x;  sy[tid] = v.y;  ss[tid] = v.z;
        const int idx = __float_as_int(v.w);
        si[tid] = idx;
        fkey[tid] = ((unsigned long long)__float_as_uint(v.z) << 32)
                  | (unsigned)(~(unsigned)idx);
    }
    __syncthreads();

    if (tid < B_SURV) {    // rank + conflict bitmask in ONE smem pass
        const unsigned long long mine = fkey[tid];
        const float x = sx[tid], y = sy[tid];
        int r = 0;
        unsigned mask = 0u;
#pragma unroll
        for (int j = 0; j < B_SURV; j++) {
            r += (fkey[j] > mine);
            const float dx = sx[j] - x;
            const float dy = sy[j] - y;
            if (dx * dx + dy * dy < NMS_THR2) mask |= (1u << j);
        }
        ord[r]  = tid;      // ranks unique (keys unique)
        cm[tid] = mask;
    }
    __syncthreads();

    if (tid == 0) {        // exact greedy scan in score order
        unsigned acc = 0u;
        int cnt = 0;
        for (int r = 0; r < B_SURV && cnt < NMS_K; r++) {
            const int j = ord[r];
            if (!(cm[j] & acc)) { sel_pos[cnt++] = j; acc |= (1u << j); }
        }
        for (; cnt < NMS_K; cnt++) sel_pos[cnt] = -1;   // fallback slots
    }
    __syncthreads();

    // Outputs. Layout: pred_trajs [B,K,T,2] | probs [B,K] | goals [B,K,2]
    float* out_prob = out + (size_t)NMS_B * NMS_K * NMS_T * 2;
    float* out_goal = out_prob + (size_t)NMS_B * NMS_K;

    if (tid < NMS_K) {
        const int  p     = sel_pos[tid];
        const bool valid = (p >= 0);
        // Fallback: reference keeps sel_idx = 0 -> sorted-first point's
        // score/traj, goal (0,0).  sel_pos[0] == ord[0] always (first is
        // always accepted).
        out_prob[(size_t)b * NMS_K + tid] = valid ? ss[p] : ss[sel_pos[0]];
        out_goal[((size_t)b * NMS_K + tid) * 2 + 0] = valid ? sx[p] : 0.0f;
        out_goal[((size_t)b * NMS_K + tid) * 2 + 1] = valid ? sy[p] : 0.0f;
    }

    if (tid < NMS_K * 15) {   // 90 float4 = all 6 traj rows, one parallel trip
        const int k = tid / 15;
        const int w = tid % 15;
        const int p = sel_pos[k];
        const int src = (p >= 0) ? si[p] : si[sel_pos[0]];
        ((float4*)out)[((size_t)b * NMS_K + k) * 15 + w] =
            ((const float4*)traj)[((size_t)b * NMS_N + src) * 15 + w];
    }
}

extern "C" void kernel_launch(void* const* d_in, const int* in_sizes, int n_in,
                              void* d_out, int out_size) {
    const float* coord = (const float*)d_in[0];  // outputs_coord     [B,1,N,2]
    const float* cls   = (const float*)d_in[1];  // outputs_class     [B,1,N]
    const float* traj  = (const float*)d_in[2];  // outputs_traj      [B,1,N,T,2]
    const float* cent  = (const float*)d_in[3];  // outputs_centerness[B,1,N]
    float* out = (float*)d_out;

    nms_persistent_kernel<<<PROD_CTAS + NMS_B, THREADS>>>(coord, cls, traj, cent, out);
}

// round 16
// speedup vs baseline: 1.5013x; 1.5013x over previous
#include <cuda_runtime.h>

// Decoder_predict: batched greedy goals-NMS.  B=256, N=4096, T=30, K=6.
// scores = class * centerness, thr^2 = 4.0.
//
// V16: clean two-kernel split (fences/atomics/spins in producers are
// measured poison; kernel boundary is the only safe sync), with kernel B's
// dependent-latency chain cut from 3 serial memory trips to ~1.5:
//  Kernel A (1024 CTAs x 256 thr; 1024 cands/CTA): stream ONLY cls+cent
//    (8.4 MB) as 2x float4/thread; per-warp top-6 by u32 score bits (exact
//    lowest-index tie-break); warp 0 rank-sorts the 48 CTA survivors
//    (count-of-greater, no shuffle chains), gathers the 6 winners' coords
//    (tiny scattered reads, overlapped across 1024 CTAs) and writes complete
//    float4 records (x, y, score, idx) -> 24 records per batch.
//  Kernel B (256 CTAs x 128 thr): one L2 record read, then IN PARALLEL:
//    warp 0 runs rank + 24x24 conflict bitmask + single-thread exact greedy
//    scan (descending score, lowest-index ties, accept iff no accepted point
//    within thr; fallback keeps sorted-first/goal-(0,0) semantics), while
//    warps 1-3 prefetch ALL 24 candidate trajectory rows into smem (the traj
//    DRAM latency hides behind the selection). One barrier, then outputs.

#define NMS_B 256
#define NMS_N 4096
#define NMS_T 30
#define NMS_K 6
#define NMS_THR2 4.0f
#define A_THREADS 256
#define CTAS_PER_B 4
#define CHUNK 1024
#define CTA_SURV 48                   // 8 warps * 6
#define B_SURV (CTAS_PER_B * NMS_K)   // 24 records per batch

__device__ float4 g_rec[NMS_B * B_SURV];   // x, y, score, idx(int bits)

// ---------------- Kernel A: stream scores, CTA top-6 records ----------------
__global__ __launch_bounds__(A_THREADS)
void score_topk_kernel(const float* __restrict__ coord,   // [B,1,N,2]
                       const float* __restrict__ cls,     // [B,1,N]
                       const float* __restrict__ cent)    // [B,1,N]
{
    const int blk  = blockIdx.x;
    const int b    = blk >> 2;
    const int q    = blk & 3;
    const int tid  = threadIdx.x;
    const int wid  = tid >> 5;
    const int lane = tid & 31;

    __shared__ unsigned long long skey[CTA_SURV];

    {
        const float4* s4 = (const float4*)(cls  + (size_t)b * NMS_N + q * CHUNK);
        const float4* e4 = (const float4*)(cent + (size_t)b * NMS_N + q * CHUNK);
        const float4 sv = s4[tid];
        const float4 ev = e4[tid];

        unsigned sc[4];
        sc[0] = __float_as_uint(sv.x * ev.x);
        sc[1] = __float_as_uint(sv.y * ev.y);
        sc[2] = __float_as_uint(sv.z * ev.z);
        sc[3] = __float_as_uint(sv.w * ev.w);
        const unsigned i0 = (unsigned)(q * CHUNK + 4 * tid);

        unsigned tmax = max(max(sc[0], sc[1]), max(sc[2], sc[3]));

#pragma unroll
        for (int r = 0; r < NMS_K; r++) {
            unsigned m = tmax;
#pragma unroll
            for (int off = 16; off > 0; off >>= 1)
                m = max(m, __shfl_xor_sync(0xFFFFFFFFu, m, off));

            if (m == 0u) {
                // Degenerate (scores exhausted): unique tiny sentinel, sorts
                // last, never collides with real keys.
                if (lane == 0)
                    skey[wid * NMS_K + r] =
                        (unsigned long long)(wid * NMS_K + r + 1);
            } else {
                const bool mine = (tmax == m);
                const unsigned bal = __ballot_sync(0xFFFFFFFFu, mine);
                const int wl = __ffs(bal) - 1;    // lowest lane = lowest idx
                if (lane == wl) {
                    int jm = 3;
#pragma unroll
                    for (int j = 3; j >= 0; j--)
                        if (sc[j] == m) jm = j;   // lowest slot = lowest idx
                    skey[wid * NMS_K + r] =
                        ((unsigned long long)m << 32) | (unsigned)(~(i0 + jm));
#pragma unroll
                    for (int j = 0; j < 4; j++) if (j == jm) sc[j] = 0u;
                    tmax = max(max(sc[0], sc[1]), max(sc[2], sc[3]));
                }
            }
        }
    }
    __syncthreads();

    // Warp 0: rank 48 survivors; winners gather coords, write full records.
    if (wid == 0) {
        const unsigned long long k0 = skey[lane];
        const unsigned long long k1 = (lane < 16) ? skey[32 + lane] : 0ULL;
        int r0 = 0, r1 = 0;
#pragma unroll
        for (int j = 0; j < CTA_SURV; j++) {
            const unsigned long long kj = skey[j];
            r0 += (kj > k0);
            r1 += (kj > k1);
        }
        const float2* cptr = (const float2*)(coord + (size_t)b * NMS_N * 2);
        float4* dst = g_rec + (size_t)b * B_SURV + q * NMS_K;
        if (r0 < NMS_K) {
            const int idx = (int)(~(unsigned)k0) & (NMS_N - 1);
            const float2 c = cptr[idx];
            dst[r0] = make_float4(c.x, c.y,
                                  __uint_as_float((unsigned)(k0 >> 32)),
                                  __int_as_float(idx));
        }
        if (lane < 16 && r1 < NMS_K) {
            const int idx = (int)(~(unsigned)k1) & (NMS_N - 1);
            const float2 c = cptr[idx];
            dst[r1] = make_float4(c.x, c.y,
                                  __uint_as_float((unsigned)(k1 >> 32)),
                                  __int_as_float(idx));
        }
    }
}

// ---------------- Kernel B: overlapped select + traj prefetch ----------------
__global__ __launch_bounds__(128)
void nms_finish_kernel(const float* __restrict__ traj,    // [B,1,N,T,2]
                       float* __restrict__ out)
{
    const int b   = blockIdx.x;
    const int tid = threadIdx.x;

    __shared__ float    sx[B_SURV], sy[B_SURV], ss[B_SURV];
    __shared__ int      si[B_SURV], ord[B_SURV];
    __shared__ unsigned long long skk[B_SURV];
    __shared__ unsigned cm[B_SURV];
    __shared__ int      sel_pos[NMS_K];
    __shared__ float4   straj[B_SURV][15];   // all 24 candidate traj rows

    // One L2 trip: read the 24 records (written by kernel A; L1 is flushed
    // at launch, stream order gives visibility).
    if (tid < B_SURV) {
        const float4 v = g_rec[(size_t)b * B_SURV + tid];
        sx[tid] = v.x;  sy[tid] = v.y;  ss[tid] = v.z;
        const int idx = __float_as_int(v.w);
        si[tid] = idx;
        skk[tid] = ((unsigned long long)__float_as_uint(v.z) << 32)
                 | (unsigned)(~(unsigned)idx);
    }
    __syncthreads();

    if (tid < 32) {
        // ---- Warp 0: rank + conflict bitmask + exact greedy scan. ----
        if (tid < B_SURV) {
            const unsigned long long mine = skk[tid];
            const float x = sx[tid], y = sy[tid];
            int r = 0;
            unsigned mask = 0u;
#pragma unroll
            for (int j = 0; j < B_SURV; j++) {
                r += (skk[j] > mine);
                const float dx = sx[j] - x;
                const float dy = sy[j] - y;
                if (dx * dx + dy * dy < NMS_THR2) mask |= (1u << j);
            }
            ord[r]  = tid;        // ranks unique (keys unique)
            cm[tid] = mask;
        }
        __syncwarp();
        if (tid == 0) {
            unsigned acc = 0u;
            int cnt = 0;
            for (int r = 0; r < B_SURV && cnt < NMS_K; r++) {
                const int j = ord[r];
                if (!(cm[j] & acc)) { sel_pos[cnt++] = j; acc |= (1u << j); }
            }
            for (; cnt < NMS_K; cnt++) sel_pos[cnt] = -1;   // fallback slots
        }
    } else {
        // ---- Warps 1-3: prefetch ALL 24 candidate traj rows into smem. ----
        // 360 float4 over 96 threads; DRAM latency hides behind the scan.
        for (int e = tid - 32; e < B_SURV * 15; e += 96) {
            const int c = e / 15;
            const int w = e % 15;
            straj[c][w] =
                ((const float4*)traj)[((size_t)b * NMS_N + si[c]) * 15 + w];
        }
    }
    __syncthreads();

    // ---- Outputs. Layout: pred_trajs [B,K,T,2] | probs [B,K] | goals [B,K,2]
    float* out_prob = out + (size_t)NMS_B * NMS_K * NMS_T * 2;
    float* out_goal = out_prob + (size_t)NMS_B * NMS_K;

    if (tid < NMS_K) {
        const int  p     = sel_pos[tid];
        const bool valid = (p >= 0);
        // Fallback: reference keeps sel_idx = 0 -> sorted-first point's
        // score/traj, goal (0,0).  sel_pos[0] == ord[0] always.
        out_prob[(size_t)b * NMS_K + tid] = valid ? ss[p] : ss[sel_pos[0]];
        out_goal[((size_t)b * NMS_K + tid) * 2 + 0] = valid ? sx[p] : 0.0f;
        out_goal[((size_t)b * NMS_K + tid) * 2 + 1] = valid ? sy[p] : 0.0f;
    }

    if (tid < NMS_K * 15) {     // 6 selected rows, smem -> gmem
        const int k = tid / 15;
        const int w = tid % 15;
        const int p = sel_pos[k];
        const int c = (p >= 0) ? p : sel_pos[0];
        ((float4*)out)[((size_t)b * NMS_K + k) * 15 + w] = straj[c][w];
    }
}

extern "C" void kernel_launch(void* const* d_in, const int* in_sizes, int n_in,
                              void* d_out, int out_size) {
    const float* coord = (const float*)d_in[0];  // outputs_coord     [B,1,N,2]
    const float* cls   = (const float*)d_in[1];  // outputs_class     [B,1,N]
    const float* traj  = (const float*)d_in[2];  // outputs_traj      [B,1,N,T,2]
    const float* cent  = (const float*)d_in[3];  // outputs_centerness[B,1,N]
    float* out = (float*)d_out;

    score_topk_kernel<<<NMS_B * CTAS_PER_B, A_THREADS>>>(coord, cls, cent);
    nms_finish_kernel<<<NMS_B, 128>>>(traj, out);
}